// round 13
// baseline (speedup 1.0000x reference)
#include <cuda_runtime.h>
#include <math.h>
#include <stdint.h>

// DPLSTMCell row-0, R13: R10 (warm-best 8.70us: 4 LDG warps + 4 cp.async warps)
// with the LDG branch's weight loads explicitly front-batched into registers.
// R1's launch_bounds(256,8) had clamped regs=32 -> real MLP was only ~2-4; this
// gives each LDG warp 8 LDG.128 (4KB) in flight. Vector loads are L1-hot and
// interleave with the FMA chain. No .nc (bypasses L1 -> warm regression R5/R7),
// no TMA (R12 regression). Fast MUFU epilogue (R7-proven).

#define H 1024
#define D 1024

__device__ __forceinline__ float warp_reduce(float v) {
    #pragma unroll
    for (int off = 16; off > 0; off >>= 1)
        v += __shfl_xor_sync(0xFFFFFFFFu, v, off);
    return v;
}

__device__ __forceinline__ float fast_tanh(float x) {
    float r;
    asm("tanh.approx.f32 %0, %1;" : "=f"(r) : "f"(x));
    return r;
}
__device__ __forceinline__ float fast_sigmoid(float x) {
    return 0.5f * fast_tanh(0.5f * x) + 0.5f;
}

__global__ __launch_bounds__(256)
void lstm_row0_dual3_kernel(const float* __restrict__ x,
                            const float* __restrict__ h,
                            const float* __restrict__ c_prev,
                            const float* __restrict__ Wih,
                            const float* __restrict__ Whh,
                            const float* __restrict__ bih,
                            const float* __restrict__ bhh,
                            float* __restrict__ out) {
    __shared__ __align__(128) float4 swh[4 * 256];  // 16KB: 4 Whh rows (async path)
    __shared__ float sums[8];

    const int n    = blockIdx.x;
    const int tid  = threadIdx.x;
    const int wid  = tid >> 5;
    const int lane = tid & 31;

    float acc = 0.0f;

    if (wid >= 4) {
        // ---- async path: Whh row for gate = wid-4 (unchanged from R10) ----
        const int gate = wid - 4;
        const float* src_base = Whh + (size_t)(gate * H + n) * D;
        #pragma unroll
        for (int i = 0; i < 8; i++) {
            const float* src = src_base + (lane + i * 32) * 4;
            const uint32_t dst = (uint32_t)__cvta_generic_to_shared(
                &swh[gate * 256 + lane + i * 32]);
            asm volatile("cp.async.cg.shared.global [%0], [%1], 16;"
                         :: "r"(dst), "l"(src) : "memory");
        }
        asm volatile("cp.async.commit_group;" ::: "memory");

        // Vector h loads (L1/L2-hot) overlap the async transfer.
        const float4* __restrict__ v4 = reinterpret_cast<const float4*>(h);
        float4 vr[8];
        #pragma unroll
        for (int i = 0; i < 8; i++)
            vr[i] = v4[lane + i * 32];

        asm volatile("cp.async.wait_group 0;" ::: "memory");
        __syncwarp();

        const float4* w4 = &swh[gate * 256];
        #pragma unroll
        for (int i = 0; i < 8; i++) {
            const float4 wv = w4[lane + i * 32];
            acc += wv.x * vr[i].x + wv.y * vr[i].y
                 + wv.z * vr[i].z + wv.w * vr[i].w;
        }
    } else {
        // ---- LDG path: Wih row for gate = wid, weights FRONT-BATCHED (MLP=8) ----
        const int gate = wid;
        const float4* __restrict__ w4 = reinterpret_cast<const float4*>(
            Wih + (size_t)(gate * H + n) * D);
        const float4* __restrict__ v4 = reinterpret_cast<const float4*>(x);

        float4 wr[8];
        #pragma unroll
        for (int i = 0; i < 8; i++)
            wr[i] = w4[lane + i * 32];

        // Vector loads are L1-hot; interleave with FMAs (no extra reg pressure).
        #pragma unroll
        for (int i = 0; i < 8; i++) {
            const float4 xv = v4[lane + i * 32];
            acc += wr[i].x * xv.x + wr[i].y * xv.y
                 + wr[i].z * xv.z + wr[i].w * xv.w;
        }
    }

    acc = warp_reduce(acc);
    if (lane == 0) sums[wid] = acc;
    __syncthreads();

    if (tid == 0) {
        // sums[g] = Wih·x for gate g ; sums[4+g] = Whh·h for gate g
        float gi = sums[0] + sums[4] + bih[n]         + bhh[n];
        float gf = sums[1] + sums[5] + bih[H + n]     + bhh[H + n];
        float gg = sums[2] + sums[6] + bih[2 * H + n] + bhh[2 * H + n];
        float go = sums[3] + sums[7] + bih[3 * H + n] + bhh[3 * H + n];

        float i_t = fast_sigmoid(gi);
        float f_t = fast_sigmoid(gf);
        float g_t = fast_tanh(gg);
        float o_t = fast_sigmoid(go);

        float c_t = f_t * c_prev[n] + i_t * g_t;
        out[n] = o_t * fast_tanh(c_t);
    }
}

extern "C" void kernel_launch(void* const* d_in, const int* in_sizes, int n_in,
                              void* d_out, int out_size) {
    const float* x      = (const float*)d_in[0];
    const float* h      = (const float*)d_in[1];
    const float* c_prev = (const float*)d_in[2];
    const float* Wih    = (const float*)d_in[3];
    const float* Whh    = (const float*)d_in[4];
    const float* bih    = (const float*)d_in[5];
    const float* bhh    = (const float*)d_in[6];
    float* out = (float*)d_out;

    lstm_row0_dual3_kernel<<<H, 256>>>(x, h, c_prev, Wih, Whh, bih, bhh, out);
}

// round 14
// speedup vs baseline: 1.1624x; 1.1624x over previous
#include <cuda_runtime.h>
#include <math.h>
#include <stdint.h>

// DPLSTMCell row-0, R14: R10 dual-path (warm-best 8.70us) x 2 outputs per block.
// Block b computes n0=b and n1=b+512. Same partition:
//   warps 0-3: Wih rows for both outputs via interleaved LDG.128 (ptxas-scheduled;
//              R13 proved front-batching hurts). ONE vector load feeds TWO fma pairs.
//   warps 4-7: Whh rows for both outputs via cp.async.cg (16 ops, 8KB in flight).
// Halves vector traffic + per-output reduce/epilogue; 512 blocks -> single wave.
// Fast MUFU epilogue (R7+). No .nc/evict/TMA (proven warm regressions).

#define H 1024
#define D 1024
#define NOUT 512   // blocks; outputs n and n+512

__device__ __forceinline__ float warp_reduce(float v) {
    #pragma unroll
    for (int off = 16; off > 0; off >>= 1)
        v += __shfl_xor_sync(0xFFFFFFFFu, v, off);
    return v;
}

__device__ __forceinline__ float fast_tanh(float x) {
    float r;
    asm("tanh.approx.f32 %0, %1;" : "=f"(r) : "f"(x));
    return r;
}
__device__ __forceinline__ float fast_sigmoid(float x) {
    return 0.5f * fast_tanh(0.5f * x) + 0.5f;
}

__global__ __launch_bounds__(256)
void lstm_row0_x2_kernel(const float* __restrict__ x,
                         const float* __restrict__ h,
                         const float* __restrict__ c_prev,
                         const float* __restrict__ Wih,
                         const float* __restrict__ Whh,
                         const float* __restrict__ bih,
                         const float* __restrict__ bhh,
                         float* __restrict__ out) {
    // async path: 4 gates x 2 outputs x 256 float4 = 32KB
    __shared__ __align__(128) float4 swh[4][2][256];
    __shared__ float sums[2][8];

    const int n0   = blockIdx.x;
    const int n1   = blockIdx.x + NOUT;
    const int tid  = threadIdx.x;
    const int wid  = tid >> 5;
    const int lane = tid & 31;

    float acc0 = 0.0f, acc1 = 0.0f;

    if (wid >= 4) {
        // ---- async path: Whh rows for gate = wid-4, both outputs ----
        const int gate = wid - 4;
        const float* s0 = Whh + (size_t)(gate * H + n0) * D;
        const float* s1 = Whh + (size_t)(gate * H + n1) * D;
        #pragma unroll
        for (int i = 0; i < 8; i++) {
            const int idx = lane + i * 32;
            uint32_t d0 = (uint32_t)__cvta_generic_to_shared(&swh[gate][0][idx]);
            uint32_t d1 = (uint32_t)__cvta_generic_to_shared(&swh[gate][1][idx]);
            asm volatile("cp.async.cg.shared.global [%0], [%1], 16;"
                         :: "r"(d0), "l"(s0 + idx * 4) : "memory");
            asm volatile("cp.async.cg.shared.global [%0], [%1], 16;"
                         :: "r"(d1), "l"(s1 + idx * 4) : "memory");
        }
        asm volatile("cp.async.commit_group;" ::: "memory");

        // Vector h (L1/L2-hot) overlaps the async transfers.
        const float4* __restrict__ v4 = reinterpret_cast<const float4*>(h);
        float4 vr[8];
        #pragma unroll
        for (int i = 0; i < 8; i++)
            vr[i] = v4[lane + i * 32];

        asm volatile("cp.async.wait_group 0;" ::: "memory");
        __syncwarp();

        #pragma unroll
        for (int i = 0; i < 8; i++) {
            const int idx = lane + i * 32;
            const float4 w0 = swh[gate][0][idx];
            const float4 w1 = swh[gate][1][idx];
            acc0 += w0.x * vr[i].x + w0.y * vr[i].y + w0.z * vr[i].z + w0.w * vr[i].w;
            acc1 += w1.x * vr[i].x + w1.y * vr[i].y + w1.z * vr[i].z + w1.w * vr[i].w;
        }
    } else {
        // ---- LDG path: Wih rows for gate = wid, both outputs, interleaved ----
        const int gate = wid;
        const float4* __restrict__ wa = reinterpret_cast<const float4*>(
            Wih + (size_t)(gate * H + n0) * D);
        const float4* __restrict__ wb = reinterpret_cast<const float4*>(
            Wih + (size_t)(gate * H + n1) * D);
        const float4* __restrict__ v4 = reinterpret_cast<const float4*>(x);
        #pragma unroll
        for (int i = 0; i < 8; i++) {
            const int idx = lane + i * 32;
            const float4 w0 = wa[idx];
            const float4 w1 = wb[idx];
            const float4 xv = v4[idx];
            acc0 += w0.x * xv.x + w0.y * xv.y + w0.z * xv.z + w0.w * xv.w;
            acc1 += w1.x * xv.x + w1.y * xv.y + w1.z * xv.z + w1.w * xv.w;
        }
    }

    acc0 = warp_reduce(acc0);
    acc1 = warp_reduce(acc1);
    if (lane == 0) {
        sums[0][wid] = acc0;
        sums[1][wid] = acc1;
    }
    __syncthreads();

    // Two epilogues on two lanes of warp 0 (independent).
    if (tid < 2) {
        const int o = tid;                 // 0 -> n0, 1 -> n1
        const int n = o ? n1 : n0;
        // sums[o][g] = Wih·x gate g ; sums[o][4+g] = Whh·h gate g
        float gi = sums[o][0] + sums[o][4] + bih[n]         + bhh[n];
        float gf = sums[o][1] + sums[o][5] + bih[H + n]     + bhh[H + n];
        float gg = sums[o][2] + sums[o][6] + bih[2 * H + n] + bhh[2 * H + n];
        float go = sums[o][3] + sums[o][7] + bih[3 * H + n] + bhh[3 * H + n];

        float i_t = fast_sigmoid(gi);
        float f_t = fast_sigmoid(gf);
        float g_t = fast_tanh(gg);
        float o_t = fast_sigmoid(go);

        float c_t = f_t * c_prev[n] + i_t * g_t;
        out[n] = o_t * fast_tanh(c_t);
    }
}

extern "C" void kernel_launch(void* const* d_in, const int* in_sizes, int n_in,
                              void* d_out, int out_size) {
    const float* x      = (const float*)d_in[0];
    const float* h      = (const float*)d_in[1];
    const float* c_prev = (const float*)d_in[2];
    const float* Wih    = (const float*)d_in[3];
    const float* Whh    = (const float*)d_in[4];
    const float* bih    = (const float*)d_in[5];
    const float* bhh    = (const float*)d_in[6];
    float* out = (float*)d_out;

    lstm_row0_x2_kernel<<<NOUT, 256>>>(x, h, c_prev, Wih, Whh, bih, bhh, out);
}